// round 1
// baseline (speedup 1.0000x reference)
#include <cuda_runtime.h>
#include <math.h>

#define B_ 64
#define T_ 1024
#define D_ 256
#define H_ 512
#define O_ 256

#define GROUPS 16
#define CPG 8              // CTAs per group (column split of H)
#define BPG (B_ / GROUPS)  // 4 batches per group
#define COLS (H_ / CPG)    // 64 output columns per CTA
#define WSTRIDE 516        // padded row stride for W slice in SMEM (conflict-free LDS.128)

// Scratch (static device allocations; in-kernel_launch alloc is forbidden)
__device__ float    g_xw[(size_t)B_ * T_ * H_];   // 128 MB: xW0, later reused as xW1
__device__ float    g_seq[(size_t)B_ * T_ * H_];  // 128 MB: layer-0 outputs
__device__ float    g_h[2][B_][H_];               // double-buffered hidden exchange
__device__ float    g_hT[B_ * H_];                // final hidden of layer 1
__device__ unsigned g_bar[GROUPS];                // per-group monotonic barrier counters

__global__ void init_kernel() {
    if (threadIdx.x < GROUPS) g_bar[threadIdx.x] = 0u;
}

// ---------------------------------------------------------------------------
// C[M,N] = A[M,K] @ B[N,K]^T + bias1[N] + bias2[N]
// 128x128 block tile, 16 K-tile, 8x8 thread tile, fp32.
// N and K are multiples of 128/16 in all uses; only M may be ragged (M=64 fc case).
// ---------------------------------------------------------------------------
__global__ void __launch_bounds__(256) sgemm_nt(
    const float* __restrict__ A, const float* __restrict__ Bm,
    const float* __restrict__ b1, const float* __restrict__ b2,
    float* __restrict__ C, int M, int N, int K)
{
    __shared__ float As[16][132];
    __shared__ float Bs[16][132];

    const int m0 = blockIdx.y * 128;
    const int n0 = blockIdx.x * 128;
    const int tid = threadIdx.x;
    const int tx = tid & 15;   // n direction
    const int ty = tid >> 4;   // m direction

    float acc[8][8];
#pragma unroll
    for (int i = 0; i < 8; i++)
#pragma unroll
        for (int j = 0; j < 8; j++) acc[i][j] = 0.f;

    for (int k0 = 0; k0 < K; k0 += 16) {
#pragma unroll
        for (int r = 0; r < 2; r++) {
            int f = tid + 256 * r;       // 0..511 float4 slots = 128 rows x 4 quads
            int row = f >> 2;
            int kq = f & 3;
            // A tile (guard ragged M)
            int m = m0 + row;
            float4 v = make_float4(0.f, 0.f, 0.f, 0.f);
            if (m < M) v = *(const float4*)(A + (size_t)m * K + k0 + kq * 4);
            As[kq * 4 + 0][row] = v.x;
            As[kq * 4 + 1][row] = v.y;
            As[kq * 4 + 2][row] = v.z;
            As[kq * 4 + 3][row] = v.w;
            // B tile (N always multiple of 128)
            int n = n0 + row;
            float4 w = *(const float4*)(Bm + (size_t)n * K + k0 + kq * 4);
            Bs[kq * 4 + 0][row] = w.x;
            Bs[kq * 4 + 1][row] = w.y;
            Bs[kq * 4 + 2][row] = w.z;
            Bs[kq * 4 + 3][row] = w.w;
        }
        __syncthreads();

#pragma unroll
        for (int k = 0; k < 16; k++) {
            float rm[8], rn[8];
            *(float4*)&rm[0] = *(const float4*)&As[k][ty * 8];
            *(float4*)&rm[4] = *(const float4*)&As[k][ty * 8 + 4];
            *(float4*)&rn[0] = *(const float4*)&Bs[k][tx * 8];
            *(float4*)&rn[4] = *(const float4*)&Bs[k][tx * 8 + 4];
#pragma unroll
            for (int i = 0; i < 8; i++)
#pragma unroll
                for (int j = 0; j < 8; j++) acc[i][j] += rm[i] * rn[j];
        }
        __syncthreads();
    }

    float bv[8];
#pragma unroll
    for (int j = 0; j < 8; j++) {
        int n = n0 + tx * 8 + j;
        bv[j] = b1[n] + b2[n];
    }
#pragma unroll
    for (int i = 0; i < 8; i++) {
        int m = m0 + ty * 8 + i;
        if (m < M) {
            float* cp = C + (size_t)m * N + n0 + tx * 8;
#pragma unroll
            for (int j = 0; j < 8; j++) cp[j] = acc[i][j] + bv[j];
        }
    }
}

// ---------------------------------------------------------------------------
// Persistent recurrent scan.  Grid = GROUPS*CPG = 128 CTAs, 256 threads.
// CTA (g,c): batches [g*4, g*4+4), output columns [c*64, c*64+64).
// W_hh slice (64 rows x 512) held in SMEM (padded), h exchanged via g_h + barrier.
// ---------------------------------------------------------------------------
#define SCAN_SMEM_FLOATS (COLS * WSTRIDE + BPG * H_ + 4 * 256)
#define SCAN_SMEM_BYTES  (SCAN_SMEM_FLOATS * 4)

template <bool STORE_SEQ, bool STORE_HT>
__global__ void __launch_bounds__(256) scan_kernel(const float* __restrict__ Whh)
{
    extern __shared__ float sm[];
    float* Wt   = sm;                       // [COLS][WSTRIDE]
    float* hb   = sm + COLS * WSTRIDE;      // [BPG][H_]
    float* part = hb + BPG * H_;            // [4][256]

    const int g = blockIdx.x >> 3;
    const int c = blockIdx.x & 7;
    const int tid = threadIdx.x;

    // Load W slice: rows c*64 .. c*64+63 of W_hh, padded stride (coalesced LDG)
    for (int i = tid; i < COLS * H_; i += 256) {
        int r = i >> 9;
        int k = i & (H_ - 1);
        Wt[r * WSTRIDE + k] = Whh[(size_t)(c * COLS + r) * H_ + k];
    }
    for (int i = tid; i < BPG * H_; i += 256) hb[i] = 0.f;  // h0 = 0
    __syncthreads();

    const int c_loc = tid & 63;   // GEMM mapping: column
    const int kg    = tid >> 6;   // GEMM mapping: K-slice (4 x 128)
    const int ob    = tid >> 6;   // reduce mapping: batch
    const int oj    = tid & 63;   // reduce mapping: column
    const int bglob = g * BPG + ob;
    const int jglob = c * COLS + oj;

    const float* xwp = g_xw + (size_t)bglob * T_ * H_ + jglob;
    const float4* w4 = (const float4*)(Wt + c_loc * WSTRIDE + kg * 128);

    unsigned target = 0;
    volatile unsigned* bar = (volatile unsigned*)&g_bar[g];

    for (int t = 0; t < T_; t++) {
        // streamed input projection for this step (hidden under the GEMM below)
        float xw_r = __ldcg(xwp + (size_t)t * H_);

        const float4* h40 = (const float4*)(hb + 0 * H_ + kg * 128);
        const float4* h41 = (const float4*)(hb + 1 * H_ + kg * 128);
        const float4* h42 = (const float4*)(hb + 2 * H_ + kg * 128);
        const float4* h43 = (const float4*)(hb + 3 * H_ + kg * 128);

        float a0 = 0.f, a1 = 0.f, a2 = 0.f, a3 = 0.f;
#pragma unroll 8
        for (int q = 0; q < 32; q++) {
            float4 w = w4[q];
            float4 v0 = h40[q];
            a0 += w.x * v0.x + w.y * v0.y + w.z * v0.z + w.w * v0.w;
            float4 v1 = h41[q];
            a1 += w.x * v1.x + w.y * v1.y + w.z * v1.z + w.w * v1.w;
            float4 v2 = h42[q];
            a2 += w.x * v2.x + w.y * v2.y + w.z * v2.z + w.w * v2.w;
            float4 v3 = h43[q];
            a3 += w.x * v3.x + w.y * v3.y + w.z * v3.z + w.w * v3.w;
        }
        part[kg * 256 +   0 + c_loc] = a0;
        part[kg * 256 +  64 + c_loc] = a1;
        part[kg * 256 + 128 + c_loc] = a2;
        part[kg * 256 + 192 + c_loc] = a3;
        __syncthreads();

        float s = part[tid] + part[256 + tid] + part[512 + tid] + part[768 + tid] + xw_r;
        float hn = tanhf(s);

        const int p = t & 1;
        g_h[p][bglob][jglob] = hn;
        if (STORE_SEQ) g_seq[((size_t)bglob * T_ + t) * H_ + jglob] = hn;
        if (STORE_HT && t == T_ - 1) g_hT[bglob * H_ + jglob] = hn;

        __threadfence();
        __syncthreads();
        if (tid == 0) {
            atomicAdd(&g_bar[g], 1u);
            target += CPG;
            while (*bar < target) { }
        }
        __syncthreads();

        // reload full group hidden state for next step (L2, bypass L1)
        const float4* src = (const float4*)(&g_h[p][g * BPG][0]);
        float4* dst = (float4*)hb;
#pragma unroll
        for (int i = 0; i < (BPG * H_ / 4) / 256; i++)
            dst[tid + 256 * i] = __ldcg(src + tid + 256 * i);
        __syncthreads();
    }
}

// ---------------------------------------------------------------------------
// fc: out[b, n] = hT[b,:] . W_fc[n,:] + b_fc[n]   (tiny: 8.4 MFLOP)
// ---------------------------------------------------------------------------
__global__ void __launch_bounds__(256) fc_kernel(
    const float* __restrict__ Wfc, const float* __restrict__ bfc,
    float* __restrict__ out)
{
    __shared__ float hs[H_];
    const int b = blockIdx.x;
    for (int i = threadIdx.x; i < H_; i += 256) hs[i] = g_hT[b * H_ + i];
    __syncthreads();

    const int n = threadIdx.x;  // 256 threads = O_
    const float4* w = (const float4*)(Wfc + (size_t)n * H_);
    const float4* h4 = (const float4*)hs;
    float acc = 0.f;
#pragma unroll 8
    for (int q = 0; q < H_ / 4; q++) {
        float4 a = w[q];
        float4 x = h4[q];
        acc += a.x * x.x + a.y * x.y + a.z * x.z + a.w * x.w;
    }
    out[b * O_ + n] = acc + bfc[n];
}

// ---------------------------------------------------------------------------

extern "C" void kernel_launch(void* const* d_in, const int* in_sizes, int n_in,
                              void* d_out, int out_size)
{
    const float* x     = (const float*)d_in[0];
    const float* W_ih0 = (const float*)d_in[1];
    const float* W_hh0 = (const float*)d_in[2];
    const float* b_ih0 = (const float*)d_in[3];
    const float* b_hh0 = (const float*)d_in[4];
    const float* W_ih1 = (const float*)d_in[5];
    const float* W_hh1 = (const float*)d_in[6];
    const float* b_ih1 = (const float*)d_in[7];
    const float* b_hh1 = (const float*)d_in[8];
    const float* W_fc  = (const float*)d_in[9];
    const float* b_fc  = (const float*)d_in[10];
    float* out = (float*)d_out;

    void* p_xw = nullptr;
    void* p_seq = nullptr;
    cudaGetSymbolAddress(&p_xw, g_xw);
    cudaGetSymbolAddress(&p_seq, g_seq);

    cudaFuncSetAttribute(scan_kernel<true, false>,
                         cudaFuncAttributeMaxDynamicSharedMemorySize, SCAN_SMEM_BYTES);
    cudaFuncSetAttribute(scan_kernel<false, true>,
                         cudaFuncAttributeMaxDynamicSharedMemorySize, SCAN_SMEM_BYTES);

    const int MT = B_ * T_;  // 65536

    // Layer 0 input projection: g_xw = x @ W_ih0^T + b_ih0 + b_hh0
    init_kernel<<<1, 32>>>();
    sgemm_nt<<<dim3(H_ / 128, MT / 128), 256>>>(
        x, W_ih0, b_ih0, b_hh0, (float*)p_xw, MT, H_, D_);

    // Layer 0 scan -> g_seq
    scan_kernel<true, false><<<GROUPS * CPG, 256, SCAN_SMEM_BYTES>>>(W_hh0);

    // Layer 1 input projection: g_xw = g_seq @ W_ih1^T + b_ih1 + b_hh1
    init_kernel<<<1, 32>>>();
    sgemm_nt<<<dim3(H_ / 128, MT / 128), 256>>>(
        (const float*)p_seq, W_ih1, b_ih1, b_hh1, (float*)p_xw, MT, H_, H_);

    // Layer 1 scan -> g_hT (final hidden only)
    scan_kernel<false, true><<<GROUPS * CPG, 256, SCAN_SMEM_BYTES>>>(W_hh1);

    // fc
    fc_kernel<<<B_, 256>>>(W_fc, b_fc, out);
}